// round 16
// baseline (speedup 1.0000x reference)
#include <cuda_runtime.h>

// SSKernelNPLR: H=256, N=64, c=1, rank=1, L=2048.
// R15:
//  K1: exact R8 cauchy (frozen; at fp32 roofline ~20us).
//  K2: four-step 1024-pt c2r iFFT: 32-pt warp-shuffle FFTs (5 shfl_xor
//      stages) over both digits, one padded-smem transpose in between,
//      2 barriers total, conflict-free smem, coalesced float4 stores.

#define NSTATE 64
#define LFULL  2048
#define MHALF  1024

typedef unsigned long long u64;

__device__ float2 g_spec[256 * 1025];   // 2.05 MB scratch spectrum

__device__ __forceinline__ u64 pk2(float lo, float hi) {
    u64 r; asm("mov.b64 %0,{%1,%2};" : "=l"(r) : "f"(lo), "f"(hi)); return r;
}
__device__ __forceinline__ void up2(u64 v, float& lo, float& hi) {
    asm("mov.b64 {%0,%1},%2;" : "=f"(lo), "=f"(hi) : "l"(v));
}
__device__ __forceinline__ u64 ffma2(u64 a, u64 b, u64 c) {
    u64 r; asm("fma.rn.f32x2 %0,%1,%2,%3;" : "=l"(r) : "l"(a), "l"(b), "l"(c)); return r;
}
__device__ __forceinline__ float frcp(float x) {
    float r; asm("rcp.approx.f32 %0,%1;" : "=f"(r) : "f"(x)); return r;
}
__device__ __forceinline__ float2 cmul(float2 a, float2 b) {
    return make_float2(a.x * b.x - a.y * b.y, a.x * b.y + a.y * b.x);
}

// ---------------- K1: Cauchy + Woodbury (R8 exact) ----------------
__global__ __launch_bounds__(128)
void cauchy_kernel(const float* __restrict__ Cin,
                   const float* __restrict__ Bin,
                   const float* __restrict__ Pin,
                   const float* __restrict__ Win,
                   const float* __restrict__ log_dt)
{
    __shared__ ulonglong2 sv2[NSTATE][4];

    const int bid   = blockIdx.x;
    const int h     = bid >> 2;
    const int chunk = bid & 3;
    const int tid   = threadIdx.x;     // 0..127
    const float dt  = expf(log_dt[h]);

    if (tid < NSTATE) {
        const int base = (h * NSTATE + tid) * 2;
        float2 b = make_float2(Bin[base], Bin[base + 1]);
        float2 c = make_float2(Cin[base], Cin[base + 1]);
        float2 p = make_float2(Pin[base], Pin[base + 1]);
        float2 q = make_float2(p.x, -p.y);          // Q = conj(P)
        u64 wd = pk2(-Win[base] * dt, -Win[base + 1] * dt);
        float2 v;
        v = cmul(b, c);
        sv2[tid][0] = make_ulonglong2(pk2(v.x, -v.x), pk2(v.y, v.y));
        v = cmul(b, q);
        sv2[tid][1] = make_ulonglong2(pk2(v.x, -v.x), pk2(v.y, v.y));
        v = cmul(p, c);
        sv2[tid][2] = make_ulonglong2(pk2(v.x, -v.x), pk2(v.y, v.y));
        float v11 = p.x * p.x + p.y * p.y;          // P*conj(P) is real
        sv2[tid][3] = make_ulonglong2(pk2(v11, -v11), wd);
    }
    __syncthreads();

    float zx[2], zy[2];
    float2 facv[2];
    #pragma unroll
    for (int k = 0; k < 2; k++) {
        const int f = chunk * 256 + k * 128 + tid;  // 0..1023
        float s, c;
        sincospif((float)f * (1.0f / MHALF), &s, &c);
        float2 om = make_float2(c, -s);             // exp(-2*pi*i*f/L)
        float ex = 1.0f + om.x, ey = om.y;          // 1 + omega
        float inv_e2 = frcp(ex * ex + ey * ey);
        float ax = 1.0f - om.x, ay = -om.y;         // 1 - omega
        zx[k] = 2.0f * (ax * ex + ay * ey) * inv_e2;
        zy[k] = 2.0f * (ay * ex - ax * ey) * inv_e2;
        facv[k] = make_float2(2.0f * ex * inv_e2, -2.0f * ey * inv_e2);
    }

    u64 acc[2][4];
    #pragma unroll
    for (int k = 0; k < 2; k++)
        #pragma unroll
        for (int a = 0; a < 4; a++) acc[k][a] = 0ull;

    #pragma unroll 4
    for (int n = 0; n < NSTATE; n++) {
        const ulonglong2 p0 = sv2[n][0];
        const ulonglong2 p1 = sv2[n][1];
        const ulonglong2 p2 = sv2[n][2];
        const ulonglong2 p3 = sv2[n][3];
        float wdx, wdy; up2(p3.y, wdx, wdy);
        #pragma unroll
        for (int k = 0; k < 2; k++) {
            float dx = zx[k] + wdx;                 // z - w*dt (pre-negated)
            float dy = zy[k] + wdy;
            float r  = frcp(dx * dx + dy * dy);
            float ur = dx * r, ui = dy * r;         // 1/d = (ur, -ui)
            u64 P1 = pk2(ur, ui);
            u64 P2 = pk2(ui, ur);
            acc[k][0] = ffma2(p0.x, P1, acc[k][0]); acc[k][0] = ffma2(p0.y, P2, acc[k][0]);
            acc[k][1] = ffma2(p1.x, P1, acc[k][1]); acc[k][1] = ffma2(p1.y, P2, acc[k][1]);
            acc[k][2] = ffma2(p2.x, P1, acc[k][2]); acc[k][2] = ffma2(p2.y, P2, acc[k][2]);
            acc[k][3] = ffma2(p3.x, P1, acc[k][3]); // v11 real: no imag term
        }
    }

    #pragma unroll
    for (int k = 0; k < 2; k++) {
        const int f = chunk * 256 + k * 128 + tid;
        float2 r00, r01, r10, r11;
        up2(acc[k][0], r00.x, r00.y); up2(acc[k][1], r01.x, r01.y);
        up2(acc[k][2], r10.x, r10.y); up2(acc[k][3], r11.x, r11.y);
        r00.x *= dt; r00.y *= dt;  r01.x *= dt; r01.y *= dt;
        r10.x *= dt; r10.y *= dt;  r11.x *= dt; r11.y *= dt;
        float2 t = cmul(r01, r10);
        float2 d = make_float2(1.0f + r11.x, r11.y);
        float iD = frcp(d.x * d.x + d.y * d.y);
        float2 t2 = make_float2((t.x * d.x + t.y * d.y) * iD,
                                (t.y * d.x - t.x * d.y) * iD);
        float2 kf = cmul(make_float2(r00.x - t2.x, r00.y - t2.y), facv[k]);
        g_spec[h * 1025 + f] = kf;
    }

    if (chunk == 0 && tid == 0) {
        float sx = 0.f, sy = 0.f;
        #pragma unroll 8
        for (int n = 0; n < NSTATE; n++) {
            float vx, vxn, vy, du;
            up2(sv2[n][0].x, vx, vxn);
            up2(sv2[n][0].y, vy, du);
            sx += vx; sy += vy;
        }
        g_spec[h * 1025 + 1024] = make_float2(0.5f * dt * sx, 0.5f * dt * sy);
    }
}

// ---------------- K2: four-step warp-shuffle c2r iFFT ----------------
// 1024 = 32 x 32, k = k1 + 32*k2, n = n2 + 32*n1.
// x[n2+32*n1] = sum_k1 e^{2pi i k1 n1/32} e^{2pi i k1 n2/1024}
//                 * sum_k2 Z[k1+32k2] e^{2pi i k2 n2/32}
// 32-pt iDFT across lanes: 5 radix-2 DIF shfl_xor stages; output at lane
// rev5(n); hi-lane twiddle e^{+2pi i (l&(m-1))/(2m)}.
__global__ __launch_bounds__(256)
void ifft_kernel(float* __restrict__ out)
{
    __shared__ float S_re[32][33],  S_im[32][33];    // pass-1 -> pass-2
    __shared__ float S2_re[32][33], S2_im[32][33];   // pass-2 -> store

    const int tid = threadIdx.x;
    const int w   = tid >> 5;                 // warp 0..7
    const int l   = tid & 31;                 // lane
    const int h   = blockIdx.x;
    const int rv  = (int)(__brev((unsigned)l) >> 27);   // rev5(l)

    // stage twiddles: tw[s] = exp(+i*pi*(l&(m-1))/m), m = 16>>s
    float twc[5], tws[5];
    #pragma unroll
    for (int s = 0; s < 5; s++) {
        int m = 16 >> s;
        sincospif((float)(l & (m - 1)) * (1.0f / (float)m), &tws[s], &twc[s]);
    }

    // ---- load + c2r pack: Z[k1 + 32*l], rows k1 = 4w+r ----
    const float2* spec = g_spec + h * 1025;
    float xr[4], xi[4];
    #pragma unroll
    for (int r = 0; r < 4; r++) {
        int k1 = 4 * w + r;
        int k  = k1 + 32 * l;                 // 0..1023
        float2 Xa = spec[k];
        float2 Xm = spec[1024 - k];
        if (k == 0) { Xa.y = 0.0f; Xm.y = 0.0f; }
        float Ex = Xa.x + Xm.x, Ey = Xa.y - Xm.y;
        float Ox = Xa.x - Xm.x, Oy = Xa.y + Xm.y;
        float s, c;
        sincospif((float)k * (1.0f / 1024.0f), &s, &c);  // W = e^{i pi k/1024}
        xr[r] = Ex - (c * Oy + s * Ox);
        xi[r] = Ey + (c * Ox - s * Oy);
    }

    // ---- inner 32-pt iFFT over k2 (lanes), 4 rows ----
    #pragma unroll
    for (int s = 0; s < 5; s++) {
        int m = 16 >> s;
        bool hi = (l & m) != 0;
        #pragma unroll
        for (int r = 0; r < 4; r++) {
            float pr = __shfl_xor_sync(0xffffffffu, xr[r], m);
            float pq = __shfl_xor_sync(0xffffffffu, xi[r], m);
            float dr = pr - xr[r], di = pq - xi[r];
            float sr = xr[r] + pr, si = xi[r] + pq;
            float rr = dr * twc[s] - di * tws[s];
            float ri = dr * tws[s] + di * twc[s];
            xr[r] = hi ? rr : sr;
            xi[r] = hi ? ri : si;
        }
    }

    // ---- mid twiddle e^{+2pi i k1*n2/1024}, n2 = rev5(l); store S[k1][n2] ----
    #pragma unroll
    for (int r = 0; r < 4; r++) {
        int k1 = 4 * w + r;
        float s, c;
        sincospif((float)(k1 * rv) * (1.0f / 512.0f), &s, &c);
        S_re[k1][rv] = xr[r] * c - xi[r] * s;
        S_im[k1][rv] = xr[r] * s + xi[r] * c;
    }
    __syncthreads();

    // ---- outer 32-pt iFFT over k1 (lanes), columns n2 = 4w+r ----
    #pragma unroll
    for (int r = 0; r < 4; r++) {
        int n2 = 4 * w + r;
        xr[r] = S_re[l][n2];
        xi[r] = S_im[l][n2];
    }
    #pragma unroll
    for (int s = 0; s < 5; s++) {
        int m = 16 >> s;
        bool hi = (l & m) != 0;
        #pragma unroll
        for (int r = 0; r < 4; r++) {
            float pr = __shfl_xor_sync(0xffffffffu, xr[r], m);
            float pq = __shfl_xor_sync(0xffffffffu, xi[r], m);
            float dr = pr - xr[r], di = pq - xi[r];
            float sr = xr[r] + pr, si = xi[r] + pq;
            float rr = dr * twc[s] - di * tws[s];
            float ri = dr * tws[s] + di * twc[s];
            xr[r] = hi ? rr : sr;
            xi[r] = hi ? ri : si;
        }
    }
    // lane l holds x[n2 + 32*rev5(l)] -> S2[n1][n2]
    #pragma unroll
    for (int r = 0; r < 4; r++) {
        int n2 = 4 * w + r;
        S2_re[rv][n2] = xr[r];
        S2_im[rv][n2] = xi[r];
    }
    __syncthreads();

    // ---- coalesced store: thread t -> n = 4t..4t+3; out[2n]=re, out[2n+1]=im ----
    const float scale = 1.0f / (float)LFULL;
    int n0  = 4 * tid;
    int row = n0 >> 5;          // n1 (constant over the 4 n's: n0%32 <= 28)
    int col = n0 & 31;          // n2 base
    float r0 = S2_re[row][col + 0] * scale, i0 = S2_im[row][col + 0] * scale;
    float r1 = S2_re[row][col + 1] * scale, i1 = S2_im[row][col + 1] * scale;
    float r2 = S2_re[row][col + 2] * scale, i2 = S2_im[row][col + 2] * scale;
    float r3 = S2_re[row][col + 3] * scale, i3 = S2_im[row][col + 3] * scale;
    float4* o4 = (float4*)(out + (size_t)h * LFULL + 8 * tid);
    o4[0] = make_float4(r0, i0, r1, i1);
    o4[1] = make_float4(r2, i2, r3, i3);
}

extern "C" void kernel_launch(void* const* d_in, const int* in_sizes, int n_in,
                              void* d_out, int out_size)
{
    (void)in_sizes; (void)n_in; (void)out_size;
    const float* C  = (const float*)d_in[0];
    const float* B  = (const float*)d_in[1];
    const float* P  = (const float*)d_in[2];
    const float* W  = (const float*)d_in[3];
    const float* ld = (const float*)d_in[4];
    float* out = (float*)d_out;
    cauchy_kernel<<<1024, 128>>>(C, B, P, W, ld);
    ifft_kernel<<<256, 256>>>(out);
}